// round 16
// baseline (speedup 1.0000x reference)
#include <cuda_runtime.h>
#include <cuda_fp16.h>
#include <mma.h>
#include <cstdint>

using namespace nvcuda;

namespace {
constexpr int NKEY = 49;
constexpr int QN_  = 196;
constexpr int DIM_ = 384;
constexpr int NH_  = 12;
constexpr int HD_  = 32;
constexpr int CQ_  = 192;
constexpr float SCALE_ = 0.17677669529663687f;

constexpr int NT    = 384;   // 12 warps
constexpr int NW    = 12;
constexpr int CHUNK = 64;
constexpr int NKP   = 64;

constexpr int SKVH = 392;    // K/V row stride (halves)
constexpr int SQP  = 392;    // qp / x row stride (halves)
constexpr int SQIN = 200;    // q-input row stride (halves)
constexpr int BSTR = 64;     // bias row stride (floats)

// smem byte offsets
constexpr int OFF_K   = 0;                // 64*392*2 = 50176
constexpr int OFF_V   = 50176;
constexpr int OFF_SCR = 100352;           // qin 64x200 half / ost 16x192 f32
constexpr int OFF_QP0 = 125952;           // 64x392 half (phase1: s_x overlays)
constexpr int OFF_QP1 = 176128;           // 64x392 half
constexpr int OFF_QC  = 226304;           // 196 ints
constexpr int OFF_ONE = 227088;
constexpr int SMEM_BYTES = 227600;

using FragA  = wmma::fragment<wmma::matrix_a, 16, 16, 16, __half, wmma::row_major>;
using FragBR = wmma::fragment<wmma::matrix_b, 16, 16, 16, __half, wmma::row_major>;
using FragBC = wmma::fragment<wmma::matrix_b, 16, 16, 16, __half, wmma::col_major>;
using FragC  = wmma::fragment<wmma::accumulator, 16, 16, 16, float>;
using FragCH = wmma::fragment<wmma::accumulator, 16, 16, 16, __half>;

constexpr int NF_KV = 25 * 48;
constexpr int NF_Q  = 13 * 24;
constexpr int NF_P  = 25 * 12;
constexpr int NFRAG = NF_KV + NF_Q + NF_P;        // 1812
constexpr int FRAG_BLOCKS = (NFRAG + 7) / 8;      // 227
constexpr int BIAS_ELEMS  = NH_ * 49 * BSTR;      // 37632
constexpr int BIAS_BLOCKS = (BIAS_ELEMS + 255) / 256;
}

__device__ uint4 g_wkv_f[NF_KV * 32];
__device__ uint4 g_wq_f [NF_Q  * 32];
__device__ uint4 g_wp_f [NF_P  * 32];
__device__ float g_bias_f[BIAS_ELEMS];

__device__ __forceinline__ void expand_b(FragBR& f, uint4 v) {
    unsigned int w[4] = {v.x, v.y, v.z, v.w};
#pragma unroll
    for (int i = 0; i < 4; ++i) {
        const __half2 h2 = *reinterpret_cast<const __half2*>(&w[i]);
        f.x[2 * i]     = __low2half(h2);
        f.x[2 * i + 1] = __high2half(h2);
    }
}

__device__ __forceinline__ void cvt_store_half(__half* dst, int ld, const FragC& c) {
    FragCH h;
#pragma unroll
    for (int i = 0; i < 8; ++i) h.x[i] = __float2half_rn(c.x[i]);
    wmma::store_matrix_sync(dst, h, ld, wmma::mem_row_major);
}

__device__ __forceinline__ void cvt_acc_to_a(FragA& a, const FragC& c) {
#pragma unroll
    for (int i = 0; i < 8; ++i) a.x[i] = __float2half_rn(c.x[i]);
}

// ---- q projection for MT m-tiles of head h; results as register A-fragments ----
template <int MT>
__device__ __forceinline__ void qproj(const __half* s_qin, FragA (&qa)[MT][2],
                                      const FragA& ones, int h, int lane)
{
    const int nt0 = h * 2;
    FragC qc[MT][2];
#pragma unroll
    for (int m = 0; m < MT; ++m) {
        wmma::fill_fragment(qc[m][0], 0.0f);
        wmma::fill_fragment(qc[m][1], 0.0f);
    }
    uint4 nb0 = g_wq_f[nt0 * 32 + lane];
    uint4 nb1 = g_wq_f[(nt0 + 1) * 32 + lane];
    for (int ks = 0; ks < 12; ++ks) {
        FragBR b0, b1;
        expand_b(b0, nb0);
        expand_b(b1, nb1);
        nb0 = g_wq_f[((ks + 1) * 24 + nt0) * 32 + lane];
        nb1 = g_wq_f[((ks + 1) * 24 + nt0 + 1) * 32 + lane];
#pragma unroll
        for (int m = 0; m < MT; ++m) {
            FragA a;
            wmma::load_matrix_sync(a, s_qin + m * 16 * SQIN + ks * 16, SQIN);
            wmma::mma_sync(qc[m][0], a, b0, qc[m][0]);
            wmma::mma_sync(qc[m][1], a, b1, qc[m][1]);
        }
    }
    {
        FragBR b0, b1;
        expand_b(b0, nb0);
        expand_b(b1, nb1);
#pragma unroll
        for (int m = 0; m < MT; ++m) {
            wmma::mma_sync(qc[m][0], ones, b0, qc[m][0]);
            wmma::mma_sync(qc[m][1], ones, b1, qc[m][1]);
        }
    }
#pragma unroll
    for (int m = 0; m < MT; ++m) {
        cvt_acc_to_a(qa[m][0], qc[m][0]);
        cvt_acc_to_a(qa[m][1], qc[m][1]);
    }
}

// ---- softmax on one 16x64 S tile (registers) -> pre-normalized half P ----
// Tiles 0..2 cover keys 0..47 (all real, no masking needed).
// Tile 3 has exactly one real key (48), owned by lanes with c0l==0.
__device__ __forceinline__ void softmax_pf(FragC (&sf)[4], FragA (&pf)[4],
                                           const float* bias0, const float* bias1,
                                           int c0l)
{
    const bool k48 = (c0l == 0);
    float mx0 = -1e30f, mx1 = -1e30f;
#pragma unroll
    for (int t = 0; t < 3; ++t) {
        const int cb = t * 16 + c0l;
        const float2 b0a = *(const float2*)(bias0 + cb);
        const float2 b0b = *(const float2*)(bias0 + cb + 8);
        const float2 b1a = *(const float2*)(bias1 + cb);
        const float2 b1b = *(const float2*)(bias1 + cb + 8);
        float v;
        v = sf[t].x[0] + b0a.x; sf[t].x[0] = v; mx0 = fmaxf(mx0, v);
        v = sf[t].x[1] + b0a.y; sf[t].x[1] = v; mx0 = fmaxf(mx0, v);
        v = sf[t].x[4] + b0b.x; sf[t].x[4] = v; mx0 = fmaxf(mx0, v);
        v = sf[t].x[5] + b0b.y; sf[t].x[5] = v; mx0 = fmaxf(mx0, v);
        v = sf[t].x[2] + b1a.x; sf[t].x[2] = v; mx1 = fmaxf(mx1, v);
        v = sf[t].x[3] + b1a.y; sf[t].x[3] = v; mx1 = fmaxf(mx1, v);
        v = sf[t].x[6] + b1b.x; sf[t].x[6] = v; mx1 = fmaxf(mx1, v);
        v = sf[t].x[7] + b1b.y; sf[t].x[7] = v; mx1 = fmaxf(mx1, v);
    }
    const float v48_0 = k48 ? sf[3].x[0] + bias0[48] : -1e30f;
    const float v48_1 = k48 ? sf[3].x[2] + bias1[48] : -1e30f;
    mx0 = fmaxf(mx0, v48_0);
    mx1 = fmaxf(mx1, v48_1);

    mx0 = fmaxf(mx0, __shfl_xor_sync(0xffffffffu, mx0, 1));
    mx0 = fmaxf(mx0, __shfl_xor_sync(0xffffffffu, mx0, 2));
    mx1 = fmaxf(mx1, __shfl_xor_sync(0xffffffffu, mx1, 1));
    mx1 = fmaxf(mx1, __shfl_xor_sync(0xffffffffu, mx1, 2));

    float s0 = 0.f, s1 = 0.f;
#pragma unroll
    for (int t = 0; t < 3; ++t) {
        float p;
        p = __expf(sf[t].x[0] - mx0); sf[t].x[0] = p; s0 += p;
        p = __expf(sf[t].x[1] - mx0); sf[t].x[1] = p; s0 += p;
        p = __expf(sf[t].x[4] - mx0); sf[t].x[4] = p; s0 += p;
        p = __expf(sf[t].x[5] - mx0); sf[t].x[5] = p; s0 += p;
        p = __expf(sf[t].x[2] - mx1); sf[t].x[2] = p; s1 += p;
        p = __expf(sf[t].x[3] - mx1); sf[t].x[3] = p; s1 += p;
        p = __expf(sf[t].x[6] - mx1); sf[t].x[6] = p; s1 += p;
        p = __expf(sf[t].x[7] - mx1); sf[t].x[7] = p; s1 += p;
    }
    const float p48_0 = k48 ? __expf(v48_0 - mx0) : 0.f;
    const float p48_1 = k48 ? __expf(v48_1 - mx1) : 0.f;
    s0 += p48_0;
    s1 += p48_1;

    s0 += __shfl_xor_sync(0xffffffffu, s0, 1);
    s0 += __shfl_xor_sync(0xffffffffu, s0, 2);
    s1 += __shfl_xor_sync(0xffffffffu, s1, 1);
    s1 += __shfl_xor_sync(0xffffffffu, s1, 2);
    const float inv0 = 1.0f / s0;
    const float inv1 = 1.0f / s1;

#pragma unroll
    for (int t = 0; t < 3; ++t) {
        pf[t].x[0] = __float2half_rn(sf[t].x[0] * inv0);
        pf[t].x[1] = __float2half_rn(sf[t].x[1] * inv0);
        pf[t].x[4] = __float2half_rn(sf[t].x[4] * inv0);
        pf[t].x[5] = __float2half_rn(sf[t].x[5] * inv0);
        pf[t].x[2] = __float2half_rn(sf[t].x[2] * inv1);
        pf[t].x[3] = __float2half_rn(sf[t].x[3] * inv1);
        pf[t].x[6] = __float2half_rn(sf[t].x[6] * inv1);
        pf[t].x[7] = __float2half_rn(sf[t].x[7] * inv1);
    }
    const __half hz = __float2half_rn(0.0f);
    pf[3].x[0] = __float2half_rn(p48_0 * inv0);
    pf[3].x[2] = __float2half_rn(p48_1 * inv1);
    pf[3].x[1] = hz; pf[3].x[3] = hz;
    pf[3].x[4] = hz; pf[3].x[5] = hz;
    pf[3].x[6] = hz; pf[3].x[7] = hz;
}

// ---- attention for a PAIR of 16-row sub-chunks: shared K/V fragment loads ----
template <bool CLAMP>
__device__ __forceinline__ void attn_pair(const FragA (&qa0)[2], const FragA (&qa1)[2],
                                          const __half* s_k, const __half* s_v,
                                          __half* dst0, __half* dst1, const int* s_qc,
                                          int row0, int h, int lane)
{
    const int base = h * HD_;
    const int r0l = lane >> 2;
    const int c0l = (lane & 3) * 2;

    FragC sf0[4], sf1[4];
#pragma unroll
    for (int t = 0; t < 4; ++t) {
        wmma::fill_fragment(sf0[t], 0.0f);
        wmma::fill_fragment(sf1[t], 0.0f);
    }
#pragma unroll
    for (int ks = 0; ks < 2; ++ks) {
#pragma unroll
        for (int t = 0; t < 4; ++t) {
            FragBC bk;
            wmma::load_matrix_sync(bk, s_k + (t * 16) * SKVH + base + ks * 16, SKVH);
            wmma::mma_sync(sf0[t], qa0[ks], bk, sf0[t]);
            wmma::mma_sync(sf1[t], qa1[ks], bk, sf1[t]);
        }
    }

    FragA pf0[4], pf1[4];
    {
        int i0 = row0 + r0l, i1 = i0 + 8;
        if (CLAMP) { i0 = min(i0, QN_ - 1); i1 = min(i1, QN_ - 1); }
        softmax_pf(sf0, pf0, g_bias_f + (h * 49 + s_qc[i0]) * BSTR,
                   g_bias_f + (h * 49 + s_qc[i1]) * BSTR, c0l);
    }
    {
        int i0 = row0 + 16 + r0l, i1 = i0 + 8;
        if (CLAMP) { i0 = min(i0, QN_ - 1); i1 = min(i1, QN_ - 1); }
        softmax_pf(sf1, pf1, g_bias_f + (h * 49 + s_qc[i0]) * BSTR,
                   g_bias_f + (h * 49 + s_qc[i1]) * BSTR, c0l);
    }

    FragC o0[2], o1[2];
    wmma::fill_fragment(o0[0], 0.0f);
    wmma::fill_fragment(o0[1], 0.0f);
    wmma::fill_fragment(o1[0], 0.0f);
    wmma::fill_fragment(o1[1], 0.0f);
#pragma unroll
    for (int ks = 0; ks < 4; ++ks) {
#pragma unroll
        for (int t = 0; t < 2; ++t) {
            FragBR bv;
            wmma::load_matrix_sync(bv, s_v + ks * 16 * SKVH + base + t * 16, SKVH);
            wmma::mma_sync(o0[t], pf0[ks], bv, o0[t]);
            wmma::mma_sync(o1[t], pf1[ks], bv, o1[t]);
        }
    }
#pragma unroll
    for (int t = 0; t < 2; ++t) {
        cvt_store_half(dst0 + base + t * 16, SQP, o0[t]);
        cvt_store_half(dst1 + base + t * 16, SQP, o1[t]);
    }
}

// ---- single-sub-chunk attention (tail) ----
__device__ __forceinline__ void attn_single(const FragA (&qa0)[2],
                                            const __half* s_k, const __half* s_v,
                                            __half* dst0, const int* s_qc,
                                            int row0, int h, int lane)
{
    const int base = h * HD_;
    const int r0l = lane >> 2;
    const int c0l = (lane & 3) * 2;

    FragC sf[4];
#pragma unroll
    for (int t = 0; t < 4; ++t) wmma::fill_fragment(sf[t], 0.0f);
#pragma unroll
    for (int ks = 0; ks < 2; ++ks) {
#pragma unroll
        for (int t = 0; t < 4; ++t) {
            FragBC bk;
            wmma::load_matrix_sync(bk, s_k + (t * 16) * SKVH + base + ks * 16, SKVH);
            wmma::mma_sync(sf[t], qa0[ks], bk, sf[t]);
        }
    }

    FragA pf[4];
    {
        int i0 = min(row0 + r0l, QN_ - 1);
        int i1 = min(row0 + r0l + 8, QN_ - 1);
        softmax_pf(sf, pf, g_bias_f + (h * 49 + s_qc[i0]) * BSTR,
                   g_bias_f + (h * 49 + s_qc[i1]) * BSTR, c0l);
    }

    FragC o[2];
    wmma::fill_fragment(o[0], 0.0f);
    wmma::fill_fragment(o[1], 0.0f);
#pragma unroll
    for (int ks = 0; ks < 4; ++ks) {
#pragma unroll
        for (int t = 0; t < 2; ++t) {
            FragBR bv;
            wmma::load_matrix_sync(bv, s_v + ks * 16 * SKVH + base + t * 16, SKVH);
            wmma::mma_sync(o[t], pf[ks], bv, o[t]);
        }
    }
#pragma unroll
    for (int t = 0; t < 2; ++t)
        cvt_store_half(dst0 + base + t * 16, SQP, o[t]);
}

// ---- out projection for MT m-tiles; warp handles n-tile nt ----
template <int MT>
__device__ __forceinline__ void out_proj_block(
    const __half* s_qpb, float* dst, int dst_ld,
    const FragA& ones, int nt, int lane)
{
    FragC c[MT];
#pragma unroll
    for (int m = 0; m < MT; ++m) wmma::fill_fragment(c[m], 0.0f);
    uint4 nb = g_wp_f[nt * 32 + lane];
    for (int ks = 0; ks < 24; ++ks) {
        FragBR bw;
        expand_b(bw, nb);
        nb = g_wp_f[((ks + 1) * 12 + nt) * 32 + lane];
#pragma unroll
        for (int m = 0; m < MT; ++m) {
            FragA a;
            wmma::load_matrix_sync(a, s_qpb + m * 16 * SQP + ks * 16, SQP);
            wmma::mma_sync(c[m], a, bw, c[m]);
        }
    }
    {
        FragBR bw;
        expand_b(bw, nb);
#pragma unroll
        for (int m = 0; m < MT; ++m) wmma::mma_sync(c[m], ones, bw, c[m]);
    }
#pragma unroll
    for (int m = 0; m < MT; ++m)
        wmma::store_matrix_sync(dst + m * 16 * dst_ld + nt * 16, c[m], dst_ld,
                                wmma::mem_row_major);
}

// ---------------- single merged setup kernel ----------------
__global__ void pack_setup(const float* __restrict__ w_kv, const float* __restrict__ b_kv,
                           const float* __restrict__ w_q,  const float* __restrict__ b_q,
                           const float* __restrict__ w_proj, const float* __restrict__ b_proj,
                           const float* __restrict__ bias_table) {
    if (blockIdx.x >= FRAG_BLOCKS) {
        const int idx = (blockIdx.x - FRAG_BLOCKS) * 256 + threadIdx.x;
        if (idx >= BIAS_ELEMS) return;
        const int key = idx & (BSTR - 1);
        const int rem = idx >> 6;            // h*49 + qc
        if (key >= NKEY) { g_bias_f[idx] = 0.0f; return; }
        const int h  = rem / 49;
        const int qc = rem - h * 49;
        const int qi2 = qc / 7, qj2 = qc - qi2 * 7;
        const int kp  = key * 4;
        const int ki  = kp / 14, kj = kp - ki * 14;
        const int dh  = qi2 - (ki >> 1) + 6;
        const int dw  = qj2 - (kj >> 1) + 6;
        g_bias_f[idx] = bias_table[(dh * 13 + dw) * NH_ + h];
        return;
    }
    __shared__ __half tiles[8][256];
    const int w    = blockIdx.x * 8 + (threadIdx.x >> 5);
    const int lane = threadIdx.x & 31;
    __half* tile = tiles[threadIdx.x >> 5];
    uint4* dst;
    if (w < NF_KV) {
        const int ks = w / 48, nt = w - ks * 48, n0 = nt * 16;
        for (int e = lane; e < 256; e += 32) {
            const int r = e >> 4, c = e & 15;
            float v;
            if (ks < 24) v = w_kv[(ks * 16 + r) * 768 + n0 + c];
            else         v = (r == 0) ? b_kv[n0 + c] : 0.0f;
            tile[e] = __float2half_rn(v);
        }
        dst = g_wkv_f + w * 32;
    } else if (w < NF_KV + NF_Q) {
        const int w2 = w - NF_KV, ks = w2 / 24, nt = w2 - ks * 24, n0 = nt * 16;
        for (int e = lane; e < 256; e += 32) {
            const int r = e >> 4, c = e & 15;
            float v;
            if (ks < 12) v = w_q[(ks * 16 + r) * DIM_ + n0 + c] * SCALE_;
            else         v = (r == 0) ? b_q[n0 + c] * SCALE_ : 0.0f;
            tile[e] = __float2half_rn(v);
        }
        dst = g_wq_f + w2 * 32;
    } else if (w < NFRAG) {
        const int w3 = w - NF_KV - NF_Q, ks = w3 / 12, nt = w3 - ks * 12, n0 = nt * 16;
        for (int e = lane; e < 256; e += 32) {
            const int r = e >> 4, c = e & 15;
            float v;
            if (ks < 24) v = w_proj[(ks * 16 + r) * CQ_ + n0 + c];
            else         v = (r == 0) ? b_proj[n0 + c] : 0.0f;
            tile[e] = __float2half_rn(v);
        }
        dst = g_wp_f + w3 * 32;
    } else return;
    __syncwarp();
    FragBR f;
    wmma::load_matrix_sync(f, tile, 16);
    unsigned int w4[4];
#pragma unroll
    for (int i = 0; i < 4; ++i) {
        __half2 h2 = __halves2half2(f.x[2 * i], f.x[2 * i + 1]);
        w4[i] = *reinterpret_cast<unsigned int*>(&h2);
    }
    dst[lane] = make_uint4(w4[0], w4[1], w4[2], w4[3]);
}

// ---------------- main kernel ----------------
__global__ __launch_bounds__(NT, 1)
void wca_kernel(const float* __restrict__ kv, const float* __restrict__ q,
                float* __restrict__ out)
{
    extern __shared__ char smb[];
    __half* s_k   = (__half*)(smb + OFF_K);
    __half* s_v   = (__half*)(smb + OFF_V);
    __half* s_qin = (__half*)(smb + OFF_SCR);
    float*  s_ost = (float*)(smb + OFF_SCR);
    __half* s_qp0 = (__half*)(smb + OFF_QP0);
    __half* s_qp1 = (__half*)(smb + OFF_QP1);
    __half* s_x   = (__half*)(smb + OFF_QP0);
    int*    s_qc  = (int*)(smb + OFF_QC);
    __half* s_one = (__half*)(smb + OFF_ONE);

    const int b    = blockIdx.x;
    const int tid  = threadIdx.x;
    const int wid  = tid >> 5;
    const int lane = tid & 31;

    // ---- phase 0: X load + pad, ones tile, bias cells, chunk-0 q-load ----
    {
        const float4* src = (const float4*)(kv + (size_t)b * NKEY * DIM_);
        for (int i = tid; i < NKEY * 96; i += NT) {
            const int r = i / 96, c4 = (i - r * 96) * 4;
            const float4 v = src[i];
            __half* d = s_x + r * SQP + c4;
            d[0] = __float2half_rn(v.x); d[1] = __float2half_rn(v.y);
            d[2] = __float2half_rn(v.z); d[3] = __float2half_rn(v.w);
        }
        for (int i = tid; i < (NKP - NKEY) * SQP; i += NT)
            s_x[NKEY * SQP + i] = __float2half_rn(0.0f);
        if (tid < 256) s_one[tid] = __float2half_rn((tid & 15) == 0 ? 1.0f : 0.0f);
        if (tid < QN_) {
            const int qi = tid / 14, qj = tid - qi * 14;
            s_qc[tid] = (qi >> 1) * 7 + (qj >> 1);
        }
        const float4* qsrc = (const float4*)(q + (size_t)b * QN_ * CQ_);
        for (int i = tid; i < CHUNK * 48; i += NT) {
            const int r = i / 48, c4 = (i - r * 48) * 4;
            const float4 v = qsrc[i];
            __half* d = s_qin + r * SQIN + c4;
            d[0] = __float2half_rn(v.x); d[1] = __float2half_rn(v.y);
            d[2] = __float2half_rn(v.z); d[3] = __float2half_rn(v.w);
        }
    }
    __syncthreads();

    FragA ones;
    wmma::load_matrix_sync(ones, s_one, 16);

    // ---- phase 1: kv projection, m-split passes (A-LDSM halved vs n-split) ----
    {
        const int nt0 = wid * 4;
        for (int pass = 0; pass < 2; ++pass) {
            const int m0 = pass * 2;
            FragC c[2][4];
#pragma unroll
            for (int m = 0; m < 2; ++m)
#pragma unroll
                for (int t = 0; t < 4; ++t) wmma::fill_fragment(c[m][t], 0.0f);
            for (int ks = 0; ks < 24; ++ks) {
                FragA a0, a1;
                wmma::load_matrix_sync(a0, s_x + (m0 * 16) * SQP + ks * 16, SQP);
                wmma::load_matrix_sync(a1, s_x + (m0 * 16 + 16) * SQP + ks * 16, SQP);
#pragma unroll
                for (int t = 0; t < 4; ++t) {
                    FragBR bb;
                    expand_b(bb, g_wkv_f[(ks * 48 + nt0 + t) * 32 + lane]);
                    wmma::mma_sync(c[0][t], a0, bb, c[0][t]);
                    wmma::mma_sync(c[1][t], a1, bb, c[1][t]);
                }
            }
#pragma unroll
            for (int t = 0; t < 4; ++t) {
                FragBR bb;
                expand_b(bb, g_wkv_f[(24 * 48 + nt0 + t) * 32 + lane]);
                wmma::mma_sync(c[0][t], ones, bb, c[0][t]);
                wmma::mma_sync(c[1][t], ones, bb, c[1][t]);
            }
#pragma unroll
            for (int t = 0; t < 4; ++t) {
                const int colg = (nt0 + t) * 16;
                __half* dst = (colg < DIM_) ? (s_k + colg) : (s_v + colg - DIM_);
                cvt_store_half(dst + m0 * 16 * SKVH, SKVH, c[0][t]);
                cvt_store_half(dst + (m0 + 1) * 16 * SKVH, SKVH, c[1][t]);
            }
        }
    }
    __syncthreads();   // K/V ready; qin(0) ready

    const size_t ob_base = (size_t)b * QN_ * CQ_;

    // ---- phase 2: 3 full chunks, pipelined out-proj ----
    for (int i = 0; i < 3; ++i) {
        const int q0 = i * CHUNK;
        __half* qpw = (i & 1) ? s_qp1 : s_qp0;

        FragA qa[4][2];
        qproj<4>(s_qin, qa, ones, wid, lane);

        if (i > 0) {
            const __half* qpr = ((i - 1) & 1) ? s_qp1 : s_qp0;
            out_proj_block<4>(qpr, out + ob_base + (size_t)(q0 - CHUNK) * CQ_,
                              CQ_, ones, wid, lane);
        }

        attn_pair<false>(qa[0], qa[1], s_k, s_v, qpw, qpw + 16 * SQP,
                         s_qc, q0, wid, lane);
        attn_pair<false>(qa[2], qa[3], s_k, s_v, qpw + 32 * SQP, qpw + 48 * SQP,
                         s_qc, q0 + 32, wid, lane);
        __syncthreads();   // O(i) complete; qin consumed

        // load next chunk's q rows
        {
            const int q0n = q0 + CHUNK;
            const int nrn = (i == 2) ? (QN_ - 3 * CHUNK) : CHUNK;   // 4 or 64
            const int mtn = (i == 2) ? 1 : 4;
            const float4* src = (const float4*)(q + ob_base + (size_t)q0n * CQ_);
            for (int e = tid; e < mtn * 16 * 48; e += NT) {
                const int r = e / 48, c4 = (e - r * 48) * 4;
                float4 v = make_float4(0.f, 0.f, 0.f, 0.f);
                if (r < nrn) v = src[e];
                __half* d = s_qin + r * SQIN + c4;
                d[0] = __float2half_rn(v.x); d[1] = __float2half_rn(v.y);
                d[2] = __float2half_rn(v.z); d[3] = __float2half_rn(v.w);
            }
            __syncthreads();
        }
    }

    // ---- tail chunk (rows 192..195, MT=1) ----
    {
        FragA qa1[1][2];
        qproj<1>(s_qin, qa1, ones, wid, lane);

        out_proj_block<4>(s_qp0, out + ob_base + (size_t)(2 * CHUNK) * CQ_,
                          CQ_, ones, wid, lane);

        attn_single(qa1[0], s_k, s_v, s_qp1, s_qc, 3 * CHUNK, wid, lane);
        __syncthreads();

        out_proj_block<1>(s_qp1, s_ost, CQ_, ones, wid, lane);
        __syncthreads();

        const int nrl = QN_ - 3 * CHUNK;   // 4
        float4* ob = (float4*)(out + ob_base + (size_t)(3 * CHUNK) * CQ_);
        for (int e = tid; e < nrl * 48; e += NT) ob[e] = ((float4*)s_ost)[e];
    }
}

extern "C" void kernel_launch(void* const* d_in, const int* in_sizes, int n_in,
                              void* d_out, int out_size) {
    const float* kv         = (const float*)d_in[0];
    const float* q          = (const float*)d_in[1];
    const float* w_kv       = (const float*)d_in[2];
    const float* b_kv       = (const float*)d_in[3];
    const float* w_q        = (const float*)d_in[4];
    const float* b_q        = (const float*)d_in[5];
    const float* bias_table = (const float*)d_in[6];
    const float* w_proj     = (const float*)d_in[7];
    const float* b_proj     = (const float*)d_in[8];
    float* out = (float*)d_out;

    const int B = in_sizes[0] / (NKEY * DIM_);              // 2048
    pack_setup<<<FRAG_BLOCKS + BIAS_BLOCKS, 256>>>(w_kv, b_kv, w_q, b_q,
                                                   w_proj, b_proj, bias_table);

    cudaFuncSetAttribute(wca_kernel, cudaFuncAttributeMaxDynamicSharedMemorySize, SMEM_BYTES);
    wca_kernel<<<B, NT, SMEM_BYTES>>>(kv, q, out);
}

// round 17
// speedup vs baseline: 1.0249x; 1.0249x over previous
#include <cuda_runtime.h>
#include <cuda_fp16.h>
#include <mma.h>
#include <cstdint>

using namespace nvcuda;

namespace {
constexpr int NKEY = 49;
constexpr int QN_  = 196;
constexpr int DIM_ = 384;
constexpr int NH_  = 12;
constexpr int HD_  = 32;
constexpr int CQ_  = 192;
constexpr float SCALE_ = 0.17677669529663687f;

constexpr int NT    = 384;   // 12 warps
constexpr int NW    = 12;
constexpr int CHUNK = 64;
constexpr int NKP   = 64;

constexpr int SKVH = 392;    // K/V row stride (halves)
constexpr int SQP  = 392;    // qp / x row stride (halves)
constexpr int SQIN = 200;    // q-input row stride (halves)
constexpr int BSTR = 64;     // bias row stride (floats)

// smem byte offsets
constexpr int OFF_K   = 0;                // 64*392*2 = 50176
constexpr int OFF_V   = 50176;
constexpr int OFF_SCR = 100352;           // qin 64x200 half / ost 16x192 f32
constexpr int OFF_QP0 = 125952;           // 64x392 half (phase1: s_x overlays)
constexpr int OFF_QP1 = 176128;           // 64x392 half
constexpr int OFF_QC  = 226304;           // 196 ints
constexpr int OFF_ONE = 227088;
constexpr int SMEM_BYTES = 227600;

using FragA  = wmma::fragment<wmma::matrix_a, 16, 16, 16, __half, wmma::row_major>;
using FragBR = wmma::fragment<wmma::matrix_b, 16, 16, 16, __half, wmma::row_major>;
using FragBC = wmma::fragment<wmma::matrix_b, 16, 16, 16, __half, wmma::col_major>;
using FragC  = wmma::fragment<wmma::accumulator, 16, 16, 16, float>;
using FragCH = wmma::fragment<wmma::accumulator, 16, 16, 16, __half>;

constexpr int NF_KV = 25 * 48;
constexpr int NF_Q  = 13 * 24;
constexpr int NF_P  = 25 * 12;
constexpr int NFRAG = NF_KV + NF_Q + NF_P;        // 1812
constexpr int FRAG_BLOCKS = (NFRAG + 7) / 8;      // 227
constexpr int BIAS_ELEMS  = NH_ * 49 * BSTR;      // 37632
constexpr int BIAS_BLOCKS = (BIAS_ELEMS + 255) / 256;
}

__device__ uint4 g_wkv_f[NF_KV * 32];
__device__ uint4 g_wq_f [NF_Q  * 32];
__device__ uint4 g_wp_f [NF_P  * 32];
__device__ float g_bias_f[BIAS_ELEMS];

__device__ __forceinline__ void expand_b(FragBR& f, uint4 v) {
    unsigned int w[4] = {v.x, v.y, v.z, v.w};
#pragma unroll
    for (int i = 0; i < 4; ++i) {
        const __half2 h2 = *reinterpret_cast<const __half2*>(&w[i]);
        f.x[2 * i]     = __low2half(h2);
        f.x[2 * i + 1] = __high2half(h2);
    }
}

__device__ __forceinline__ void cvt_store_half(__half* dst, int ld, const FragC& c) {
    FragCH h;
#pragma unroll
    for (int i = 0; i < 8; ++i) h.x[i] = __float2half_rn(c.x[i]);
    wmma::store_matrix_sync(dst, h, ld, wmma::mem_row_major);
}

__device__ __forceinline__ void cvt_acc_to_a(FragA& a, const FragC& c) {
#pragma unroll
    for (int i = 0; i < 8; ++i) a.x[i] = __float2half_rn(c.x[i]);
}

// ---- q projection for MT m-tiles of head h; results as register A-fragments ----
template <int MT>
__device__ __forceinline__ void qproj(const __half* s_qin, FragA (&qa)[MT][2],
                                      const FragA& ones, int h, int lane)
{
    const int nt0 = h * 2;
    FragC qc[MT][2];
#pragma unroll
    for (int m = 0; m < MT; ++m) {
        wmma::fill_fragment(qc[m][0], 0.0f);
        wmma::fill_fragment(qc[m][1], 0.0f);
    }
    uint4 nb0 = g_wq_f[nt0 * 32 + lane];
    uint4 nb1 = g_wq_f[(nt0 + 1) * 32 + lane];
    for (int ks = 0; ks < 12; ++ks) {
        FragBR b0, b1;
        expand_b(b0, nb0);
        expand_b(b1, nb1);
        nb0 = g_wq_f[((ks + 1) * 24 + nt0) * 32 + lane];
        nb1 = g_wq_f[((ks + 1) * 24 + nt0 + 1) * 32 + lane];
#pragma unroll
        for (int m = 0; m < MT; ++m) {
            FragA a;
            wmma::load_matrix_sync(a, s_qin + m * 16 * SQIN + ks * 16, SQIN);
            wmma::mma_sync(qc[m][0], a, b0, qc[m][0]);
            wmma::mma_sync(qc[m][1], a, b1, qc[m][1]);
        }
    }
    {
        FragBR b0, b1;
        expand_b(b0, nb0);
        expand_b(b1, nb1);
#pragma unroll
        for (int m = 0; m < MT; ++m) {
            wmma::mma_sync(qc[m][0], ones, b0, qc[m][0]);
            wmma::mma_sync(qc[m][1], ones, b1, qc[m][1]);
        }
    }
#pragma unroll
    for (int m = 0; m < MT; ++m) {
        cvt_acc_to_a(qa[m][0], qc[m][0]);
        cvt_acc_to_a(qa[m][1], qc[m][1]);
    }
}

// ---- softmax on one 16x64 S tile (registers) -> pre-normalized half P ----
// Tiles 0..2 cover keys 0..47 (all real, no masking needed).
// Tile 3 has exactly one real key (48), owned by lanes with c0l==0.
__device__ __forceinline__ void softmax_pf(FragC (&sf)[4], FragA (&pf)[4],
                                           const float* bias0, const float* bias1,
                                           int c0l)
{
    const bool k48 = (c0l == 0);
    float mx0 = -1e30f, mx1 = -1e30f;
#pragma unroll
    for (int t = 0; t < 3; ++t) {
        const int cb = t * 16 + c0l;
        const float2 b0a = *(const float2*)(bias0 + cb);
        const float2 b0b = *(const float2*)(bias0 + cb + 8);
        const float2 b1a = *(const float2*)(bias1 + cb);
        const float2 b1b = *(const float2*)(bias1 + cb + 8);
        float v;
        v = sf[t].x[0] + b0a.x; sf[t].x[0] = v; mx0 = fmaxf(mx0, v);
        v = sf[t].x[1] + b0a.y; sf[t].x[1] = v; mx0 = fmaxf(mx0, v);
        v = sf[t].x[4] + b0b.x; sf[t].x[4] = v; mx0 = fmaxf(mx0, v);
        v = sf[t].x[5] + b0b.y; sf[t].x[5] = v; mx0 = fmaxf(mx0, v);
        v = sf[t].x[2] + b1a.x; sf[t].x[2] = v; mx1 = fmaxf(mx1, v);
        v = sf[t].x[3] + b1a.y; sf[t].x[3] = v; mx1 = fmaxf(mx1, v);
        v = sf[t].x[6] + b1b.x; sf[t].x[6] = v; mx1 = fmaxf(mx1, v);
        v = sf[t].x[7] + b1b.y; sf[t].x[7] = v; mx1 = fmaxf(mx1, v);
    }
    const float v48_0 = k48 ? sf[3].x[0] + bias0[48] : -1e30f;
    const float v48_1 = k48 ? sf[3].x[2] + bias1[48] : -1e30f;
    mx0 = fmaxf(mx0, v48_0);
    mx1 = fmaxf(mx1, v48_1);

    mx0 = fmaxf(mx0, __shfl_xor_sync(0xffffffffu, mx0, 1));
    mx0 = fmaxf(mx0, __shfl_xor_sync(0xffffffffu, mx0, 2));
    mx1 = fmaxf(mx1, __shfl_xor_sync(0xffffffffu, mx1, 1));
    mx1 = fmaxf(mx1, __shfl_xor_sync(0xffffffffu, mx1, 2));

    float s0 = 0.f, s1 = 0.f;
#pragma unroll
    for (int t = 0; t < 3; ++t) {
        float p;
        p = __expf(sf[t].x[0] - mx0); sf[t].x[0] = p; s0 += p;
        p = __expf(sf[t].x[1] - mx0); sf[t].x[1] = p; s0 += p;
        p = __expf(sf[t].x[4] - mx0); sf[t].x[4] = p; s0 += p;
        p = __expf(sf[t].x[5] - mx0); sf[t].x[5] = p; s0 += p;
        p = __expf(sf[t].x[2] - mx1); sf[t].x[2] = p; s1 += p;
        p = __expf(sf[t].x[3] - mx1); sf[t].x[3] = p; s1 += p;
        p = __expf(sf[t].x[6] - mx1); sf[t].x[6] = p; s1 += p;
        p = __expf(sf[t].x[7] - mx1); sf[t].x[7] = p; s1 += p;
    }
    const float p48_0 = k48 ? __expf(v48_0 - mx0) : 0.f;
    const float p48_1 = k48 ? __expf(v48_1 - mx1) : 0.f;
    s0 += p48_0;
    s1 += p48_1;

    s0 += __shfl_xor_sync(0xffffffffu, s0, 1);
    s0 += __shfl_xor_sync(0xffffffffu, s0, 2);
    s1 += __shfl_xor_sync(0xffffffffu, s1, 1);
    s1 += __shfl_xor_sync(0xffffffffu, s1, 2);
    const float inv0 = 1.0f / s0;
    const float inv1 = 1.0f / s1;

#pragma unroll
    for (int t = 0; t < 3; ++t) {
        pf[t].x[0] = __float2half_rn(sf[t].x[0] * inv0);
        pf[t].x[1] = __float2half_rn(sf[t].x[1] * inv0);
        pf[t].x[4] = __float2half_rn(sf[t].x[4] * inv0);
        pf[t].x[5] = __float2half_rn(sf[t].x[5] * inv0);
        pf[t].x[2] = __float2half_rn(sf[t].x[2] * inv1);
        pf[t].x[3] = __float2half_rn(sf[t].x[3] * inv1);
        pf[t].x[6] = __float2half_rn(sf[t].x[6] * inv1);
        pf[t].x[7] = __float2half_rn(sf[t].x[7] * inv1);
    }
    const __half hz = __float2half_rn(0.0f);
    pf[3].x[0] = __float2half_rn(p48_0 * inv0);
    pf[3].x[2] = __float2half_rn(p48_1 * inv1);
    pf[3].x[1] = hz; pf[3].x[3] = hz;
    pf[3].x[4] = hz; pf[3].x[5] = hz;
    pf[3].x[6] = hz; pf[3].x[7] = hz;
}

// ---- attention for a PAIR of 16-row sub-chunks: shared K/V fragment loads ----
template <bool CLAMP>
__device__ __forceinline__ void attn_pair(const FragA (&qa0)[2], const FragA (&qa1)[2],
                                          const __half* s_k, const __half* s_v,
                                          __half* dst0, __half* dst1, const int* s_qc,
                                          int row0, int h, int lane)
{
    const int base = h * HD_;
    const int r0l = lane >> 2;
    const int c0l = (lane & 3) * 2;

    FragC sf0[4], sf1[4];
#pragma unroll
    for (int t = 0; t < 4; ++t) {
        wmma::fill_fragment(sf0[t], 0.0f);
        wmma::fill_fragment(sf1[t], 0.0f);
    }
#pragma unroll
    for (int ks = 0; ks < 2; ++ks) {
#pragma unroll
        for (int t = 0; t < 4; ++t) {
            FragBC bk;
            wmma::load_matrix_sync(bk, s_k + (t * 16) * SKVH + base + ks * 16, SKVH);
            wmma::mma_sync(sf0[t], qa0[ks], bk, sf0[t]);
            wmma::mma_sync(sf1[t], qa1[ks], bk, sf1[t]);
        }
    }

    FragA pf0[4], pf1[4];
    {
        int i0 = row0 + r0l, i1 = i0 + 8;
        if (CLAMP) { i0 = min(i0, QN_ - 1); i1 = min(i1, QN_ - 1); }
        softmax_pf(sf0, pf0, g_bias_f + (h * 49 + s_qc[i0]) * BSTR,
                   g_bias_f + (h * 49 + s_qc[i1]) * BSTR, c0l);
    }
    {
        int i0 = row0 + 16 + r0l, i1 = i0 + 8;
        if (CLAMP) { i0 = min(i0, QN_ - 1); i1 = min(i1, QN_ - 1); }
        softmax_pf(sf1, pf1, g_bias_f + (h * 49 + s_qc[i0]) * BSTR,
                   g_bias_f + (h * 49 + s_qc[i1]) * BSTR, c0l);
    }

    FragC o0[2], o1[2];
    wmma::fill_fragment(o0[0], 0.0f);
    wmma::fill_fragment(o0[1], 0.0f);
    wmma::fill_fragment(o1[0], 0.0f);
    wmma::fill_fragment(o1[1], 0.0f);
#pragma unroll
    for (int ks = 0; ks < 4; ++ks) {
#pragma unroll
        for (int t = 0; t < 2; ++t) {
            FragBR bv;
            wmma::load_matrix_sync(bv, s_v + ks * 16 * SKVH + base + t * 16, SKVH);
            wmma::mma_sync(o0[t], pf0[ks], bv, o0[t]);
            wmma::mma_sync(o1[t], pf1[ks], bv, o1[t]);
        }
    }
#pragma unroll
    for (int t = 0; t < 2; ++t) {
        cvt_store_half(dst0 + base + t * 16, SQP, o0[t]);
        cvt_store_half(dst1 + base + t * 16, SQP, o1[t]);
    }
}

// ---- single-sub-chunk attention (tail) ----
__device__ __forceinline__ void attn_single(const FragA (&qa0)[2],
                                            const __half* s_k, const __half* s_v,
                                            __half* dst0, const int* s_qc,
                                            int row0, int h, int lane)
{
    const int base = h * HD_;
    const int r0l = lane >> 2;
    const int c0l = (lane & 3) * 2;

    FragC sf[4];
#pragma unroll
    for (int t = 0; t < 4; ++t) wmma::fill_fragment(sf[t], 0.0f);
#pragma unroll
    for (int ks = 0; ks < 2; ++ks) {
#pragma unroll
        for (int t = 0; t < 4; ++t) {
            FragBC bk;
            wmma::load_matrix_sync(bk, s_k + (t * 16) * SKVH + base + ks * 16, SKVH);
            wmma::mma_sync(sf[t], qa0[ks], bk, sf[t]);
        }
    }

    FragA pf[4];
    {
        int i0 = min(row0 + r0l, QN_ - 1);
        int i1 = min(row0 + r0l + 8, QN_ - 1);
        softmax_pf(sf, pf, g_bias_f + (h * 49 + s_qc[i0]) * BSTR,
                   g_bias_f + (h * 49 + s_qc[i1]) * BSTR, c0l);
    }

    FragC o[2];
    wmma::fill_fragment(o[0], 0.0f);
    wmma::fill_fragment(o[1], 0.0f);
#pragma unroll
    for (int ks = 0; ks < 4; ++ks) {
#pragma unroll
        for (int t = 0; t < 2; ++t) {
            FragBR bv;
            wmma::load_matrix_sync(bv, s_v + ks * 16 * SKVH + base + t * 16, SKVH);
            wmma::mma_sync(o[t], pf[ks], bv, o[t]);
        }
    }
#pragma unroll
    for (int t = 0; t < 2; ++t)
        cvt_store_half(dst0 + base + t * 16, SQP, o[t]);
}

// ---- out projection for MT m-tiles; warp handles n-tile nt ----
template <int MT>
__device__ __forceinline__ void out_proj_block(
    const __half* s_qpb, float* dst, int dst_ld,
    const FragA& ones, int nt, int lane)
{
    FragC c[MT];
#pragma unroll
    for (int m = 0; m < MT; ++m) wmma::fill_fragment(c[m], 0.0f);
    uint4 nb = g_wp_f[nt * 32 + lane];
    for (int ks = 0; ks < 24; ++ks) {
        FragBR bw;
        expand_b(bw, nb);
        nb = g_wp_f[((ks + 1) * 12 + nt) * 32 + lane];
#pragma unroll
        for (int m = 0; m < MT; ++m) {
            FragA a;
            wmma::load_matrix_sync(a, s_qpb + m * 16 * SQP + ks * 16, SQP);
            wmma::mma_sync(c[m], a, bw, c[m]);
        }
    }
    {
        FragBR bw;
        expand_b(bw, nb);
#pragma unroll
        for (int m = 0; m < MT; ++m) wmma::mma_sync(c[m], ones, bw, c[m]);
    }
#pragma unroll
    for (int m = 0; m < MT; ++m)
        wmma::store_matrix_sync(dst + m * 16 * dst_ld + nt * 16, c[m], dst_ld,
                                wmma::mem_row_major);
}

// ---------------- single merged setup kernel ----------------
__global__ void pack_setup(const float* __restrict__ w_kv, const float* __restrict__ b_kv,
                           const float* __restrict__ w_q,  const float* __restrict__ b_q,
                           const float* __restrict__ w_proj, const float* __restrict__ b_proj,
                           const float* __restrict__ bias_table) {
    if (blockIdx.x >= FRAG_BLOCKS) {
        const int idx = (blockIdx.x - FRAG_BLOCKS) * 256 + threadIdx.x;
        if (idx >= BIAS_ELEMS) return;
        const int key = idx & (BSTR - 1);
        const int rem = idx >> 6;            // h*49 + qc
        if (key >= NKEY) { g_bias_f[idx] = 0.0f; return; }
        const int h  = rem / 49;
        const int qc = rem - h * 49;
        const int qi2 = qc / 7, qj2 = qc - qi2 * 7;
        const int kp  = key * 4;
        const int ki  = kp / 14, kj = kp - ki * 14;
        const int dh  = qi2 - (ki >> 1) + 6;
        const int dw  = qj2 - (kj >> 1) + 6;
        g_bias_f[idx] = bias_table[(dh * 13 + dw) * NH_ + h];
        return;
    }
    __shared__ __half tiles[8][256];
    const int w    = blockIdx.x * 8 + (threadIdx.x >> 5);
    const int lane = threadIdx.x & 31;
    __half* tile = tiles[threadIdx.x >> 5];
    uint4* dst;
    if (w < NF_KV) {
        const int ks = w / 48, nt = w - ks * 48, n0 = nt * 16;
        for (int e = lane; e < 256; e += 32) {
            const int r = e >> 4, c = e & 15;
            float v;
            if (ks < 24) v = w_kv[(ks * 16 + r) * 768 + n0 + c];
            else         v = (r == 0) ? b_kv[n0 + c] : 0.0f;
            tile[e] = __float2half_rn(v);
        }
        dst = g_wkv_f + w * 32;
    } else if (w < NF_KV + NF_Q) {
        const int w2 = w - NF_KV, ks = w2 / 24, nt = w2 - ks * 24, n0 = nt * 16;
        for (int e = lane; e < 256; e += 32) {
            const int r = e >> 4, c = e & 15;
            float v;
            if (ks < 12) v = w_q[(ks * 16 + r) * DIM_ + n0 + c] * SCALE_;
            else         v = (r == 0) ? b_q[n0 + c] * SCALE_ : 0.0f;
            tile[e] = __float2half_rn(v);
        }
        dst = g_wq_f + w2 * 32;
    } else if (w < NFRAG) {
        const int w3 = w - NF_KV - NF_Q, ks = w3 / 12, nt = w3 - ks * 12, n0 = nt * 16;
        for (int e = lane; e < 256; e += 32) {
            const int r = e >> 4, c = e & 15;
            float v;
            if (ks < 24) v = w_proj[(ks * 16 + r) * CQ_ + n0 + c];
            else         v = (r == 0) ? b_proj[n0 + c] : 0.0f;
            tile[e] = __float2half_rn(v);
        }
        dst = g_wp_f + w3 * 32;
    } else return;
    __syncwarp();
    FragBR f;
    wmma::load_matrix_sync(f, tile, 16);
    unsigned int w4[4];
#pragma unroll
    for (int i = 0; i < 4; ++i) {
        __half2 h2 = __halves2half2(f.x[2 * i], f.x[2 * i + 1]);
        w4[i] = *reinterpret_cast<unsigned int*>(&h2);
    }
    dst[lane] = make_uint4(w4[0], w4[1], w4[2], w4[3]);
}

// ---------------- main kernel ----------------
__global__ __launch_bounds__(NT, 1)
void wca_kernel(const float* __restrict__ kv, const float* __restrict__ q,
                float* __restrict__ out)
{
    extern __shared__ char smb[];
    __half* s_k   = (__half*)(smb + OFF_K);
    __half* s_v   = (__half*)(smb + OFF_V);
    __half* s_qin = (__half*)(smb + OFF_SCR);
    float*  s_ost = (float*)(smb + OFF_SCR);
    __half* s_qp0 = (__half*)(smb + OFF_QP0);
    __half* s_qp1 = (__half*)(smb + OFF_QP1);
    __half* s_x   = (__half*)(smb + OFF_QP0);
    int*    s_qc  = (int*)(smb + OFF_QC);
    __half* s_one = (__half*)(smb + OFF_ONE);

    const int b    = blockIdx.x;
    const int tid  = threadIdx.x;
    const int wid  = tid >> 5;
    const int lane = tid & 31;

    // ---- phase 0: X load + pad, ones tile, bias cells, chunk-0 q-load ----
    {
        const float4* src = (const float4*)(kv + (size_t)b * NKEY * DIM_);
        for (int i = tid; i < NKEY * 96; i += NT) {
            const int r = i / 96, c4 = (i - r * 96) * 4;
            const float4 v = src[i];
            __half* d = s_x + r * SQP + c4;
            d[0] = __float2half_rn(v.x); d[1] = __float2half_rn(v.y);
            d[2] = __float2half_rn(v.z); d[3] = __float2half_rn(v.w);
        }
        for (int i = tid; i < (NKP - NKEY) * SQP; i += NT)
            s_x[NKEY * SQP + i] = __float2half_rn(0.0f);
        if (tid < 256) s_one[tid] = __float2half_rn((tid & 15) == 0 ? 1.0f : 0.0f);
        if (tid < QN_) {
            const int qi = tid / 14, qj = tid - qi * 14;
            s_qc[tid] = (qi >> 1) * 7 + (qj >> 1);
        }
        const float4* qsrc = (const float4*)(q + (size_t)b * QN_ * CQ_);
        for (int i = tid; i < CHUNK * 48; i += NT) {
            const int r = i / 48, c4 = (i - r * 48) * 4;
            const float4 v = qsrc[i];
            __half* d = s_qin + r * SQIN + c4;
            d[0] = __float2half_rn(v.x); d[1] = __float2half_rn(v.y);
            d[2] = __float2half_rn(v.z); d[3] = __float2half_rn(v.w);
        }
    }
    __syncthreads();

    FragA ones;
    wmma::load_matrix_sync(ones, s_one, 16);

    // ---- phase 1: kv projection, B-stationary over 4 m-tiles (R14 form) ----
    {
        for (int j = 0; j < 2; ++j) {
            const int nt0 = (wid * 2 + j) * 2;
            FragC c[4][2];
#pragma unroll
            for (int m = 0; m < 4; ++m) {
                wmma::fill_fragment(c[m][0], 0.0f);
                wmma::fill_fragment(c[m][1], 0.0f);
            }
            uint4 nb0 = g_wkv_f[nt0 * 32 + lane];
            uint4 nb1 = g_wkv_f[(nt0 + 1) * 32 + lane];
            for (int ks = 0; ks < 24; ++ks) {
                FragBR b0, b1;
                expand_b(b0, nb0);
                expand_b(b1, nb1);
                nb0 = g_wkv_f[((ks + 1) * 48 + nt0) * 32 + lane];
                nb1 = g_wkv_f[((ks + 1) * 48 + nt0 + 1) * 32 + lane];
#pragma unroll
                for (int m = 0; m < 4; ++m) {
                    FragA a;
                    wmma::load_matrix_sync(a, s_x + m * 16 * SQP + ks * 16, SQP);
                    wmma::mma_sync(c[m][0], a, b0, c[m][0]);
                    wmma::mma_sync(c[m][1], a, b1, c[m][1]);
                }
            }
            {
                FragBR b0, b1;
                expand_b(b0, nb0);
                expand_b(b1, nb1);
#pragma unroll
                for (int m = 0; m < 4; ++m) {
                    wmma::mma_sync(c[m][0], ones, b0, c[m][0]);
                    wmma::mma_sync(c[m][1], ones, b1, c[m][1]);
                }
            }
#pragma unroll
            for (int t = 0; t < 2; ++t) {
                const int colg = (nt0 + t) * 16;
                __half* dst = (colg < DIM_) ? (s_k + colg) : (s_v + colg - DIM_);
#pragma unroll
                for (int m = 0; m < 4; ++m)
                    cvt_store_half(dst + m * 16 * SKVH, SKVH, c[m][t]);
            }
        }
    }
    __syncthreads();   // K/V ready; qin(0) ready

    const size_t ob_base = (size_t)b * QN_ * CQ_;

    // ---- phase 2: 3 full chunks, pipelined out-proj ----
    for (int i = 0; i < 3; ++i) {
        const int q0 = i * CHUNK;
        __half* qpw = (i & 1) ? s_qp1 : s_qp0;

        FragA qa[4][2];
        qproj<4>(s_qin, qa, ones, wid, lane);

        if (i > 0) {
            const __half* qpr = ((i - 1) & 1) ? s_qp1 : s_qp0;
            out_proj_block<4>(qpr, out + ob_base + (size_t)(q0 - CHUNK) * CQ_,
                              CQ_, ones, wid, lane);
        }

        attn_pair<false>(qa[0], qa[1], s_k, s_v, qpw, qpw + 16 * SQP,
                         s_qc, q0, wid, lane);
        attn_pair<false>(qa[2], qa[3], s_k, s_v, qpw + 32 * SQP, qpw + 48 * SQP,
                         s_qc, q0 + 32, wid, lane);
        __syncthreads();   // O(i) complete; qin consumed

        // load next chunk's q rows
        {
            const int q0n = q0 + CHUNK;
            const int nrn = (i == 2) ? (QN_ - 3 * CHUNK) : CHUNK;   // 4 or 64
            const int mtn = (i == 2) ? 1 : 4;
            const float4* src = (const float4*)(q + ob_base + (size_t)q0n * CQ_);
            for (int e = tid; e < mtn * 16 * 48; e += NT) {
                const int r = e / 48, c4 = (e - r * 48) * 4;
                float4 v = make_float4(0.f, 0.f, 0.f, 0.f);
                if (r < nrn) v = src[e];
                __half* d = s_qin + r * SQIN + c4;
                d[0] = __float2half_rn(v.x); d[1] = __float2half_rn(v.y);
                d[2] = __float2half_rn(v.z); d[3] = __float2half_rn(v.w);
            }
            __syncthreads();
        }
    }

    // ---- tail chunk (rows 192..195, MT=1) ----
    {
        FragA qa1[1][2];
        qproj<1>(s_qin, qa1, ones, wid, lane);

        out_proj_block<4>(s_qp0, out + ob_base + (size_t)(2 * CHUNK) * CQ_,
                          CQ_, ones, wid, lane);

        attn_single(qa1[0], s_k, s_v, s_qp1, s_qc, 3 * CHUNK, wid, lane);
        __syncthreads();

        out_proj_block<1>(s_qp1, s_ost, CQ_, ones, wid, lane);
        __syncthreads();

        const int nrl = QN_ - 3 * CHUNK;   // 4
        float4* ob = (float4*)(out + ob_base + (size_t)(3 * CHUNK) * CQ_);
        for (int e = tid; e < nrl * 48; e += NT) ob[e] = ((float4*)s_ost)[e];
    }
}

extern "C" void kernel_launch(void* const* d_in, const int* in_sizes, int n_in,
                              void* d_out, int out_size) {
    const float* kv         = (const float*)d_in[0];
    const float* q          = (const float*)d_in[1];
    const float* w_kv       = (const float*)d_in[2];
    const float* b_kv       = (const float*)d_in[3];
    const float* w_q        = (const float*)d_in[4];
    const float* b_q        = (const float*)d_in[5];
    const float* bias_table = (const float*)d_in[6];
    const float* w_proj     = (const float*)d_in[7];
    const float* b_proj     = (const float*)d_in[8];
    float* out = (float*)d_out;

    const int B = in_sizes[0] / (NKEY * DIM_);              // 2048
    pack_setup<<<FRAG_BLOCKS + BIAS_BLOCKS, 256>>>(w_kv, b_kv, w_q, b_q,
                                                   w_proj, b_proj, bias_table);

    cudaFuncSetAttribute(wca_kernel, cudaFuncAttributeMaxDynamicSharedMemorySize, SMEM_BYTES);
    wca_kernel<<<B, NT, SMEM_BYTES>>>(kv, q, out);
}